// round 10
// baseline (speedup 1.0000x reference)
#include <cuda_runtime.h>
#include <stdint.h>

// SpikeFP32GELUExact: [B,S,32] bit-pulses -> decode fp32 -> exact fp64 tanh-GELU
// -> round fp32 -> encode [B,S,32] bit-pulses. Bit 0 = MSB.
//
// Warp-cooperative layout: each warp owns 32 consecutive elements (a 32x32 bit
// matrix = 4KB). Loads/stores are fully coalesced 128B LDG.32/STG.32; the bit
// transpose is done with __ballot_sync + __brev (pack) and __shfl_sync (unpack).
// GELU math mirrors the reference's fp64 op sequence exactly: every mul/add is
// individually rounded (no FMA contraction), division is IEEE-correct, exp is
// CUDA's <1-ulp double exp.

__global__ void __launch_bounds__(256)
spike_gelu_kernel(const uint32_t* __restrict__ xu,
                  uint32_t* __restrict__ outu,
                  int n_elem)
{
    const int lane        = threadIdx.x & 31;
    const int warp_global = (blockIdx.x * blockDim.x + threadIdx.x) >> 5;
    const int base        = warp_global * 32;           // first element this warp owns
    if (base >= n_elem) return;

    const size_t off = (size_t)base * 32;               // word offset of the 32x32 block

    // ---- Load: lane l reads bit-position l of element (base+i). 128B coalesced. ----
    uint32_t v[32];
#pragma unroll
    for (int i = 0; i < 32; i++) {
        v[i] = xu[off + (size_t)i * 32 + lane];         // 0x00000000 or 0x3F800000
    }

    // ---- Transpose via ballot: after brev, bit l (MSB-first) lands correctly. ----
    uint32_t myu = 0;
#pragma unroll
    for (int i = 0; i < 32; i++) {
        unsigned b = __ballot_sync(0xffffffffu, v[i] != 0u);
        uint32_t u = __brev(b);
        if (lane == i) myu = u;
    }

    // ---- Exact GELU, fp64, mirroring reference rounding step-for-step. ----
    const float  xf = __uint_as_float(myu);
    const double x  = (double)xf;

    double x2    = __dmul_rn(x, x);                     // x*x
    double x3    = __dmul_rn(x2, x);                    // (x*x)*x
    double inner = __dadd_rn(x, __dmul_rn(0.044715, x3));
    double two_z = __dmul_rn(2.0, __dmul_rn(0.7978845608028654, inner));
    double e     = exp(two_z);                          // fp64 exp (<1 ulp)
    double th    = __ddiv_rn(__dadd_rn(e, -1.0), __dadd_rn(e, 1.0));
    double y     = __dmul_rn(0.5, __dmul_rn(x, __dadd_rn(1.0, th)));

    const uint32_t uy = __float_as_uint(__double2float_rn(y));

    // ---- Store: broadcast element i's word to all lanes; lane l writes bit l. ----
#pragma unroll
    for (int i = 0; i < 32; i++) {
        uint32_t ui  = __shfl_sync(0xffffffffu, uy, i);
        uint32_t bit = (ui >> (31 - lane)) & 1u;
        outu[off + (size_t)i * 32 + lane] = bit ? 0x3F800000u : 0u;  // 1.0f or 0.0f
    }
}

extern "C" void kernel_launch(void* const* d_in, const int* in_sizes, int n_in,
                              void* d_out, int out_size)
{
    const uint32_t* x   = (const uint32_t*)d_in[0];
    uint32_t*       out = (uint32_t*)d_out;

    const int n_elem  = in_sizes[0] / 32;               // 1024*4096 = 4,194,304
    const int threads = 256;                            // 8 warps = 256 elements/block
    const int blocks  = (n_elem + 255) / 256;

    spike_gelu_kernel<<<blocks, threads>>>(x, out, n_elem);
}

// round 13
// speedup vs baseline: 1.1135x; 1.1135x over previous
#include <cuda_runtime.h>
#include <stdint.h>

// SpikeFP32GELUExact — relaxed-fp64 fast path + reference-noise mimic + exact replica.
//
// R11/R12 post-mortem: both failed with IDENTICAL rel_err ~0.0295 => wrong set is
// data-determined: for x<0 with em=e^{2z} small, the REFERENCE's (e-1)/(e+1) then
// 1+tanh cancels catastrophically (noise 2^-54/em; outputs -0.0 for em<2^-54).
// My accurate paths computed the TRUE value => mismatch. Fix: for x<0, em<2^-17,
// MIMIC the reference's fp64 rounding sequence using the fast table-exp em.
// (em-1) quantizes at abs 2^-53 >> em*2^-44 = em's error => bit-identical result.
// Elsewhere: accurate path + integer boundary window (dist<2^18 units, margin
// 2^-35 rel >> ref noise 2^-36.4 + my err 2^-43) -> exact replica on window hit.

__device__ double g_T[64];

__global__ void fill_table_kernel() {
    int j = threadIdx.x;
    if (j < 64) g_T[j] = exp2((double)j * 0.015625);   // 2^(j/64)
}

constexpr double SHIFT  = 6755399441055744.0;           // 1.5 * 2^52
constexpr double INVL64 = 92.33248261689366;            // 64 / ln2
constexpr double L64HI  = 0.6931471805599453 / 64.0;    // exact /64
constexpr double L64LO  = 2.3190468138462996e-17 / 64.0;

// Exact replica of the reference fp64 op sequence (R10: proven bit-perfect).
__device__ __noinline__ uint32_t gelu_exact_ref(float xf) {
    double xd  = (double)xf;
    double x2d = __dmul_rn(xd, xd);
    double x3d = __dmul_rn(x2d, xd);
    double ind = __dadd_rn(xd, __dmul_rn(0.044715, x3d));
    double twz = __dmul_rn(2.0, __dmul_rn(0.7978845608028654, ind));
    double e   = exp(twz);
    double th  = __ddiv_rn(__dadd_rn(e, -1.0), __dadd_rn(e, 1.0));
    double yd  = __dmul_rn(0.5, __dmul_rn(xd, __dadd_rn(1.0, th)));
    return __float_as_uint(__double2float_rn(yd));
}

__device__ __forceinline__ uint32_t gelu_bits(uint32_t ux, const double* __restrict__ sT) {
    const float  xf = __uint_as_float(ux);
    const double x  = (double)xf;

    // two_z: EXACT replica of reference rounding (separate mul + add, two muls).
    const double x3    = __dmul_rn(__dmul_rn(x, x), x);
    const double inner = __dadd_rn(x, __dmul_rn(0.044715, x3));
    const double two_z = __dmul_rn(2.0, __dmul_rn(0.7978845608028654, inner));

    const int ihi = __double2hiint(two_z);
    const int iah = ihi & 0x7fffffff;
    if (iah >= 0x40540000)                              // |2z| >= 80, or NaN
        return gelu_exact_ref(xf);

    // em = exp(-|2z|) via shift-trick + 2^(j/64) table + deg-4 Horner (rel err ~2^-44)
    const double w  = __hiloint2double(iah | (int)0x80000000, __double2loint(two_z));
    const double tt = __fma_rn(w, INVL64, SHIFT);
    const int    k  = __double2loint(tt);
    const double kd = __dadd_rn(tt, -SHIFT);
    double r = __fma_rn(kd, -L64HI, w);
    r = __fma_rn(kd, -L64LO, r);

    double p = __fma_rn(0.041666666666666664, r, 0.16666666666666666);
    p = __fma_rn(p, r, 0.5);
    p = __fma_rn(p, r, 1.0);
    p = __fma_rn(p, r, 1.0);

    double T = sT[k & 63];
    T = __hiloint2double(__double2hiint(T) + ((k >> 6) << 20), __double2loint(T));
    const double em = __dmul_rn(T, p);

    // Deep-negative mimic: x<0 and em < 2^-17. Reproduce the reference's own
    // rounding sequence (incl. its 1+tanh cancellation noise and the exact -0.0
    // saturation for em < 2^-54) using em in place of e. Bit-identical because
    // em's abs error (<= em*2^-43) is invisible below the 2^-53 grid of (em-1).
    if (ihi < 0 && __double2hiint(em) < 0x3EE00000) {
        double th = __ddiv_rn(__dadd_rn(em, -1.0), __dadd_rn(em, 1.0));
        double ym = __dmul_rn(0.5, __dmul_rn(x, __dadd_rn(1.0, th)));
        return __float_as_uint(__double2float_rn(ym));
    }

    // Accurate path: y = x*u/(1+em), u = (x>=0 ? 1 : em). fp32 rcp seed + 1 Newton.
    const double w1 = __dadd_rn(em, 1.0);               // in (1, 2]
    double rc = (double)__frcp_rn((float)w1);
    rc = __dmul_rn(rc, __fma_rn(-w1, rc, 2.0));         // rel err ~2^-46
    const double nmr = (ihi < 0) ? __dmul_rn(x, em) : x;
    const double y   = __dmul_rn(nmr, rc);

    const float f = __double2float_rn(y);
    uint32_t bits_y = __float_as_uint(f);

    // Integer boundary window: fp32 midpoints at tail==2^28 (mod 2^29) in y's
    // fp64 mantissa. Fallback within 2^18 units (2^-35 rel margin), or subnormal.
    const int tail = __double2loint(y) & 0x1fffffff;
    int dist = tail - 0x10000000;
    dist = (dist < 0) ? -dist : dist;
    if (dist < 0x40000 || (bits_y & 0x7f800000u) == 0u)
        return gelu_exact_ref(xf);
    return bits_y;
}

__global__ void __launch_bounds__(256)
spike_gelu_kernel(const uint32_t* __restrict__ xu,
                  uint32_t* __restrict__ outu,
                  int n_elem)
{
    __shared__ double sT[64];
    if (threadIdx.x < 64) sT[threadIdx.x] = g_T[threadIdx.x];
    __syncthreads();

    const int lane        = threadIdx.x & 31;
    const int warp_global = (blockIdx.x * blockDim.x + threadIdx.x) >> 5;
    const int base        = warp_global * 32;
    if (base >= n_elem) return;

    const size_t off = (size_t)base * 32;

    // Load: lane l reads bit-position l of element (base+i). Fully coalesced.
    uint32_t v[32];
#pragma unroll
    for (int i = 0; i < 32; i++)
        v[i] = xu[off + (size_t)i * 32 + lane];

    // Transpose via ballot: bit 0 = MSB after brev.
    uint32_t myu = 0;
#pragma unroll
    for (int i = 0; i < 32; i++) {
        unsigned b = __ballot_sync(0xffffffffu, v[i] != 0u);
        uint32_t u = __brev(b);
        if (lane == i) myu = u;
    }

    const uint32_t uy = gelu_bits(myu, sT);

    // Store: broadcast element i's word; lane l writes bit l.
#pragma unroll
    for (int i = 0; i < 32; i++) {
        uint32_t ui  = __shfl_sync(0xffffffffu, uy, i);
        uint32_t bit = (ui >> (31 - lane)) & 1u;
        outu[off + (size_t)i * 32 + lane] = bit ? 0x3F800000u : 0u;
    }
}

extern "C" void kernel_launch(void* const* d_in, const int* in_sizes, int n_in,
                              void* d_out, int out_size)
{
    const uint32_t* x   = (const uint32_t*)d_in[0];
    uint32_t*       out = (uint32_t*)d_out;

    const int n_elem  = in_sizes[0] / 32;               // 1024*4096
    const int threads = 256;
    const int blocks  = (n_elem + 255) / 256;

    fill_table_kernel<<<1, 64>>>();
    spike_gelu_kernel<<<blocks, threads>>>(x, out, n_elem);
}

// round 15
// speedup vs baseline: 1.1551x; 1.0374x over previous
#include <cuda_runtime.h>
#include <stdint.h>

// SpikeFP32GELUExact — lean relaxed-fp64 fast path + mimic + analytic saturation.
//
// R13 (passed, 266us, rel_err 0.0) structure kept; R14 trims fp64 warp-ops:
//  - |2z|>=80: reference output is forced (-0.0 for x<0; x itself for x>0,
//    since e<2^-54 => RN(e-1)=-1 => th=-1; e>2^54 => th rounds to exactly 1).
//    Direct bit return, no libm (was ~10% of warps calling gelu_exact_ref).
//  - two_z: RN(2*RN(c*i)) == RN((2c)*i) exactly; inner via 1 FMA (<=1ulp dev,
//    em rel dev <=2^-45.6, inside all margins)  -> 4 ops.
//  - reduction: kd = (double)k exact I2F        -> 3 ops.
//  - e^r: s = r + r^2/2 + r^2*(r*c), c in fp32 (err enters *r^2 => 2^-47.5),
//    em = fma(T,s,T)                            -> 4 ops.
// Mimic band (x<0, em<2^-17): reference's own DDIV sequence with em (em abs err
// <= em*2^-45 << 2^-54 grid of em-1 => bit-identical). Window detector D=2^18
// units (2^-11 ulp32) covers ref tanh-cancellation noise (<=2^16 units) and my
// error (~2^8.5 units); hits (+ inf/nan) -> exact fp64 replica.

__device__ double g_T[64];

__global__ void fill_table_kernel() {
    int j = threadIdx.x;
    if (j < 64) g_T[j] = exp2((double)j * 0.015625);   // 2^(j/64)
}

constexpr double SHIFT  = 6755399441055744.0;           // 1.5 * 2^52
constexpr double INVL64 = 92.33248261689366;            // 64 / ln2
constexpr double L64HI  = 0.6931471805599453 / 64.0;    // double(ln2)/64, exact scale
constexpr double L64LO  = 2.3190468138462996e-17 / 64.0;
constexpr double K2     = 2.0 * 0.7978845608028654;     // exact doubling

// Exact replica of the reference fp64 op sequence (R10: proven bit-perfect).
__device__ __noinline__ uint32_t gelu_exact_ref(float xf) {
    double xd  = (double)xf;
    double x2d = __dmul_rn(xd, xd);
    double x3d = __dmul_rn(x2d, xd);
    double ind = __dadd_rn(xd, __dmul_rn(0.044715, x3d));
    double twz = __dmul_rn(2.0, __dmul_rn(0.7978845608028654, ind));
    double e   = exp(twz);
    double th  = __ddiv_rn(__dadd_rn(e, -1.0), __dadd_rn(e, 1.0));
    double yd  = __dmul_rn(0.5, __dmul_rn(xd, __dadd_rn(1.0, th)));
    return __float_as_uint(__double2float_rn(yd));
}

__device__ __forceinline__ uint32_t gelu_bits(uint32_t ux, const double* __restrict__ sT) {
    const float  xf = __uint_as_float(ux);
    const double x  = (double)xf;

    // two_z: RN((2c)*inner) == ref's RN(2*RN(c*inner)); inner FMA dev <= 1 ulp.
    const double x3    = __dmul_rn(__dmul_rn(x, x), x);
    const double inner = __fma_rn(0.044715, x3, x);
    const double two_z = __dmul_rn(K2, inner);

    const int ihi = __double2hiint(two_z);
    const int iah = ihi & 0x7fffffff;
    if (iah >= 0x40540000) {                            // |2z| >= 80, inf, nan
        if (iah >= 0x7ff00000) return gelu_exact_ref(xf);
        return (ihi < 0) ? 0x80000000u : ux;            // forced -0.0 / identity
    }

    // em = exp(-|2z|): shift-trick k, 2-FMA Cody-Waite (full-precision hi via FMA)
    const double w  = __hiloint2double(iah | (int)0x80000000, __double2loint(two_z));
    const double tt = __fma_rn(w, INVL64, SHIFT);
    const int    k  = __double2loint(tt);
    const double kd = (double)k;                        // exact I2F
    double r = __fma_rn(kd, -L64HI, w);
    r = __fma_rn(kd, -L64LO, r);                        // |r| <= ln2/128, err ~2^-59

    // e^r = 1 + s, s = r + r^2/2 + r^2*(r*c); c in fp32 (err scaled by r^2)
    const float rf  = (float)r;
    const float cf  = fmaf(rf, fmaf(rf, 8.3333333e-3f, 4.1666667e-2f), 0.16666667f);
    const float rcf = __fmul_rn(rf, cf);                // ~ r/6, rel err ~2^-22.5
    const double r2 = __dmul_rn(r, r);
    const double s1 = __fma_rn(0.5, r2, r);
    const double s  = __fma_rn(r2, (double)rcf, s1);    // s abs err ~2^-47.5

    double T = sT[k & 63];
    T = __hiloint2double(__double2hiint(T) + ((k >> 6) << 20), __double2loint(T));
    const double em = __fma_rn(T, s, T);                // T*(1+s), rel err ~2^-45

    // Deep-negative mimic (x<0, em<2^-17): reference's own rounding sequence;
    // em abs error <= em*2^-45 invisible below (em-1)'s 2^-53 grid.
    if (ihi < 0 && __double2hiint(em) < 0x3EE00000) {
        double th = __ddiv_rn(__dadd_rn(em, -1.0), __dadd_rn(em, 1.0));
        double ym = __dmul_rn(0.5, __dmul_rn(x, __dadd_rn(1.0, th)));
        return __float_as_uint(__double2float_rn(ym));
    }

    // Accurate path: y = x*u/(1+em), u = (x>=0 ? 1 : em); rcp seed + 1 Newton.
    const double w1 = __dadd_rn(em, 1.0);               // (1, 2]
    double rc = (double)__frcp_rn((float)w1);
    rc = __dmul_rn(rc, __fma_rn(-w1, rc, 2.0));         // rel err ~2^-44
    const double nmr = (ihi < 0) ? __dmul_rn(x, em) : x;
    const double y   = __dmul_rn(nmr, rc);

    const float f = __double2float_rn(y);
    uint32_t bits_y = __float_as_uint(f);

    // Integer boundary window on y's fp64 mantissa tail (midpoint at 2^28 mod 2^29).
    const int tail = __double2loint(y) & 0x1fffffff;
    int dist = tail - 0x10000000;
    dist = (dist < 0) ? -dist : dist;
    if (dist < 0x40000 || (bits_y & 0x7f800000u) == 0u)
        return gelu_exact_ref(xf);
    return bits_y;
}

__global__ void __launch_bounds__(256)
spike_gelu_kernel(const uint32_t* __restrict__ xu,
                  uint32_t* __restrict__ outu,
                  int n_elem)
{
    __shared__ double sT[64];
    if (threadIdx.x < 64) sT[threadIdx.x] = g_T[threadIdx.x];
    __syncthreads();

    const int lane        = threadIdx.x & 31;
    const int warp_global = (blockIdx.x * blockDim.x + threadIdx.x) >> 5;
    const int base        = warp_global * 32;
    if (base >= n_elem) return;

    const size_t off = (size_t)base * 32;

    // Load: lane l reads bit-position l of element (base+i). Fully coalesced.
    uint32_t v[32];
#pragma unroll
    for (int i = 0; i < 32; i++)
        v[i] = xu[off + (size_t)i * 32 + lane];

    // Transpose via ballot: bit 0 = MSB after brev.
    uint32_t myu = 0;
#pragma unroll
    for (int i = 0; i < 32; i++) {
        unsigned b = __ballot_sync(0xffffffffu, v[i] != 0u);
        uint32_t u = __brev(b);
        if (lane == i) myu = u;
    }

    const uint32_t uy = gelu_bits(myu, sT);

    // Store: broadcast element i's word; lane l writes bit l.
#pragma unroll
    for (int i = 0; i < 32; i++) {
        uint32_t ui  = __shfl_sync(0xffffffffu, uy, i);
        uint32_t bit = (ui >> (31 - lane)) & 1u;
        outu[off + (size_t)i * 32 + lane] = bit ? 0x3F800000u : 0u;
    }
}

extern "C" void kernel_launch(void* const* d_in, const int* in_sizes, int n_in,
                              void* d_out, int out_size)
{
    const uint32_t* x   = (const uint32_t*)d_in[0];
    uint32_t*       out = (uint32_t*)d_out;

    const int n_elem  = in_sizes[0] / 32;               // 1024*4096
    const int threads = 256;
    const int blocks  = (n_elem + 255) / 256;

    fill_table_kernel<<<1, 64>>>();
    spike_gelu_kernel<<<blocks, threads>>>(x, out, n_elem);
}